// round 16
// baseline (speedup 1.0000x reference)
#include <cuda_runtime.h>
#include <cstdint>

#define BATCH 2048
#define NCLS  1000
#define DIM   128
#define TM 128
#define TN 128
#define NCTA 128
#define SROW 132            // f32 smem row stride in floats (528B: conflict-free)

// deterministic likelihood partials + completion ticket
__device__ __align__(16) float g_part[NCTA];
__device__ int g_ticket;

// ---- smem byte offsets ----
#define OFF_A   0                       // A f32 tile: 128 x 528B = 67584
#define OFF_B   67584                   // B f32 tile: 128 x 528B = 67584
#define OFF_FNP 135168                  // float[128][4] feat norm partials
#define OFF_CNP 137216                  // float[128][4] center norm partials
#define OFF_FNC 139264                  // float[128] 0.5*||f||^2
#define OFF_CNC 139776                  // float[128] 0.5*||c||^2
#define OFF_RED 140288                  // float[16] warp partials
#define SMEM_BYTES 140352

static __device__ __forceinline__ uint32_t smem_u32(const void* p) {
    uint32_t a;
    asm("{ .reg .u64 t; cvta.to.shared.u64 t, %1; cvt.u32.u64 %0, t; }"
        : "=r"(a) : "l"(p));
    return a;
}

static __device__ __forceinline__ int get_label(const void* lab, int b, int is64) {
    if (is64) return (int)(((const long long*)lab)[b]);
    return ((const int*)lab)[b];
}

static __device__ __forceinline__ void cp_async16(uint32_t saddr, const void* gptr) {
    asm volatile("cp.async.cg.shared.global [%0], [%1], 16;"
                 :: "r"(saddr), "l"(gptr) : "memory");
}
// zero-fill variant: src-size selects 16 (copy) or 0 (write 16B of zeros)
static __device__ __forceinline__ void cp_async16z(uint32_t saddr, const void* gptr,
                                                   uint32_t srcsz) {
    asm volatile("cp.async.cg.shared.global [%0], [%1], 16, %2;"
                 :: "r"(saddr), "l"(gptr), "r"(srcsz) : "memory");
}

// m16n8k8 tf32 MMA: raw f32 bits in A/B registers (HW truncates to tf32)
#define MMA1688(d, a0, a1, a2, a3, b0, b1)                                      \
    asm volatile("mma.sync.aligned.m16n8k8.row.col.f32.tf32.tf32.f32 "          \
        "{%0,%1,%2,%3}, {%4,%5,%6,%7}, {%8,%9}, {%0,%1,%2,%3};"                 \
        : "+f"((d)[0]), "+f"((d)[1]), "+f"((d)[2]), "+f"((d)[3])                \
        : "r"(a0), "r"(a1), "r"(a2), "r"(a3), "r"(b0), "r"(b1))

// ---------------------------------------------------------------------------
// Single kernel: cp.async f32 tiles -> in-smem norms -> tf32 MMA -> epilogue.
// Grid (8,16): CTA (x,y) -> rows [128y,128y+128) x cols [128x,128x+128).
// ---------------------------------------------------------------------------
__global__ void __launch_bounds__(512, 1)
lgm_tf32_kernel(const float* __restrict__ feat,
                const void*  __restrict__ label,
                const float* __restrict__ centers,
                float* __restrict__ logits,
                float* __restrict__ mlogits,
                float* __restrict__ lik)
{
    extern __shared__ char smem[];
    const uint32_t sb = smem_u32(smem);
    float* smf = (float*)smem;
    const int tid = threadIdx.x;
    const int wid  = tid >> 5;
    const int lane = tid & 31;
    const int bb = blockIdx.y * TM;      // feat-row base
    const int cc = blockIdx.x * TN;      // center-col base

    // label dtype probe loads (overlap with staging): words <= 255, in-bounds
    int hw = 0;
    if (tid < 128) hw = (((const int*)label)[2 * tid + 1] != 0);

    // ------------- staging: cp.async f32 tiles (B zero-filled past NCLS) -----
    {
        const char* srcA = (const char*)(feat + (size_t)bb * DIM);
        const uint32_t soff = (tid >> 5) * 528 + (tid & 31) * 16;   // row,16B col
#pragma unroll
        for (int j = 0; j < 8; j++)
            cp_async16(sb + OFF_A + j * 16 * 528 + soff, srcA + j * 8192 + tid * 16);
#pragma unroll
        for (int j = 0; j < 8; j++) {
            const int crow = cc + j * 16 + (tid >> 5);
            const int cr = crow < NCLS ? crow : NCLS - 1;
            cp_async16z(sb + OFF_B + j * 16 * 528 + soff,
                        (const char*)(centers + (size_t)cr * DIM) + (tid & 31) * 16,
                        crow < NCLS ? 16u : 0u);
        }
        asm volatile("cp.async.commit_group;" ::: "memory");
    }
    asm volatile("cp.async.wait_group 0;" ::: "memory");
    const int is64 = !__syncthreads_or(hw);   // barrier: tiles visible

    // ------------- preload epilogue labels (overlaps norm pass) --------------
    const int wm = wid & 3;
    const int wn = wid >> 2;
    const int g  = lane >> 2;
    const int tc = lane & 3;
    int labs[4];
#pragma unroll
    for (int mi = 0; mi < 2; mi++)
#pragma unroll
        for (int rr = 0; rr < 2; rr++)
            labs[mi * 2 + rr] =
                get_label(label, bb + wm * 32 + mi * 16 + g + rr * 8, is64);

    // ------------- norms from smem tiles (exact f32) -------------------------
    {
        const int r = tid & 127, q = tid >> 7;   // row, 32-col quarter
        const float4* ar = (const float4*)(smf + r * SROW + q * 32);
        const float4* br = (const float4*)(smf + OFF_B / 4 + r * SROW + q * 32);
        float sa = 0.f, sc = 0.f;
#pragma unroll
        for (int i = 0; i < 8; i++) {
            float4 v = ar[i];
            sa += v.x * v.x + v.y * v.y + v.z * v.z + v.w * v.w;
            float4 w = br[i];
            sc += w.x * w.x + w.y * w.y + w.z * w.z + w.w * w.w;
        }
        ((float*)(smem + OFF_FNP))[r * 4 + q] = sa;
        ((float*)(smem + OFF_CNP))[r * 4 + q] = sc;
    }
    __syncthreads();
    if (tid < 128) {
        const float* fp = (const float*)(smem + OFF_FNP) + tid * 4;
        const float* cp = (const float*)(smem + OFF_CNP) + tid * 4;
        ((float*)(smem + OFF_FNC))[tid] = 0.5f * ((fp[0] + fp[1]) + (fp[2] + fp[3]));
        ((float*)(smem + OFF_CNC))[tid] = 0.5f * ((cp[0] + cp[1]) + (cp[2] + cp[3]));
    }
    __syncthreads();

    // ------------- tf32 mainloop: warp = 32(M) x 32(N), K in 16 steps of 8 ---
    // A frag (m16k8): a0=(g,tc) a1=(g+8,tc) a2=(g,tc+4) a3=(g+8,tc+4)
    // B frag (k8n8):  b0=(k=tc,n=g) b1=(k=tc+4,n=g); B stored [n][k]
    const uint32_t* ap = (const uint32_t*)(smf + (wm * 32 + g) * SROW + tc);
    const uint32_t* bp = (const uint32_t*)(smf + OFF_B / 4 + (wn * 32 + g) * SROW + tc);

    float acc[2][4][4] = {};
#pragma unroll
    for (int k8 = 0; k8 < 16; k8++) {
        const int ko = k8 * 8;
        uint32_t a[2][4], b[4][2];
#pragma unroll
        for (int mi = 0; mi < 2; mi++) {
            const uint32_t* p = ap + mi * 16 * SROW + ko;
            a[mi][0] = p[0];
            a[mi][2] = p[4];
            a[mi][1] = p[8 * SROW];
            a[mi][3] = p[8 * SROW + 4];
        }
#pragma unroll
        for (int nb = 0; nb < 4; nb++) {
            const uint32_t* p = bp + nb * 8 * SROW + ko;
            b[nb][0] = p[0];
            b[nb][1] = p[4];
        }
#pragma unroll
        for (int mi = 0; mi < 2; mi++)
#pragma unroll
            for (int nb = 0; nb < 4; nb++)
                MMA1688(acc[mi][nb], a[mi][0], a[mi][1], a[mi][2], a[mi][3],
                        b[nb][0], b[nb][1]);
    }

    // ------------- direct-store epilogue -------------------------------------
    const float* fnc = (const float*)(smem + OFF_FNC);
    const float* cnc = (const float*)(smem + OFF_CNC);

    float lacc = 0.f;
#pragma unroll
    for (int mi = 0; mi < 2; mi++) {
#pragma unroll
        for (int rr = 0; rr < 2; rr++) {
            const int rloc = wm * 32 + mi * 16 + g + rr * 8;
            const int m  = bb + rloc;
            const float fn = fnc[rloc];
            const int lb = labs[mi * 2 + rr];
#pragma unroll
            for (int nb = 0; nb < 4; nb++) {
                const int cloc = wn * 32 + nb * 8 + tc * 2;
                const int c = cc + cloc;
                const float2 cn = *(const float2*)(cnc + cloc);
                const float d0 = acc[mi][nb][rr * 2 + 0];
                const float d1 = acc[mi][nb][rr * 2 + 1];
                // logits = -0.5*dist = dot - 0.5||f||^2 - 0.5||c||^2
                const float lg0 = d0 - fn - cn.x;
                const float lg1 = d1 - fn - cn.y;
                float ml0 = lg0, ml1 = lg1;
                if (lb == c)     { ml0 = 2.f * lg0; lacc += lg0; }
                if (lb == c + 1) { ml1 = 2.f * lg1; lacc += lg1; }
                if (c < NCLS) {
                    const size_t off = (size_t)m * NCLS + c;
                    *(float2*)(logits + off)  = make_float2(lg0, lg1);
                    *(float2*)(mlogits + off) = make_float2(ml0, ml1);
                }
            }
        }
    }

    // ------------- likelihood: warp reduce -> CTA partial -> last CTA ---------
#pragma unroll
    for (int o = 16; o > 0; o >>= 1)
        lacc += __shfl_xor_sync(0xffffffffu, lacc, o);
    float* red = (float*)(smem + OFF_RED);
    if (lane == 0) red[wid] = lacc;
    __syncthreads();

    if (tid == 0) {
        float s = (((red[0] + red[1]) + (red[2] + red[3]))
                 + ((red[4] + red[5]) + (red[6] + red[7])))
                + (((red[8] + red[9]) + (red[10] + red[11]))
                 + ((red[12] + red[13]) + (red[14] + red[15])));
        const int cid = blockIdx.y * 8 + blockIdx.x;
        g_part[cid] = s;
        __threadfence();
        int t = atomicAdd(&g_ticket, 1);
        if (t == NCTA - 1) {
            __threadfence();
            // fixed-order, fixed-split sum => deterministic
            float a0 = 0.f, a1 = 0.f, a2 = 0.f, a3 = 0.f;
            const float4* p4 = (const float4*)g_part;
#pragma unroll
            for (int i = 0; i < NCTA / 4; i++) {
                float4 v = p4[i];
                a0 += v.x; a1 += v.y; a2 += v.z; a3 += v.w;
            }
            *lik = -((a0 + a1) + (a2 + a3)) * (1.f / (float)BATCH);
            g_ticket = 0;          // reset for next graph replay
        }
    }
}

extern "C" void kernel_launch(void* const* d_in, const int* in_sizes, int n_in,
                              void* d_out, int out_size) {
    const float* feat    = (const float*)d_in[0];
    const void*  label   = d_in[1];
    const float* centers = (const float*)d_in[2];

    float* out     = (float*)d_out;
    float* logits  = out;                              // [B, C]
    float* mlogits = out + (size_t)BATCH * NCLS;       // [B, C]
    float* lik     = out + 2 * (size_t)BATCH * NCLS;   // scalar

    cudaFuncSetAttribute(lgm_tf32_kernel,
                         cudaFuncAttributeMaxDynamicSharedMemorySize, SMEM_BYTES);

    dim3 grid(8, 16);   // 128 CTAs of 128x128 — single launch, no prepass
    lgm_tf32_kernel<<<grid, 512, SMEM_BYTES>>>(feat, label, centers,
                                               logits, mlogits, lik);
}

// round 17
// speedup vs baseline: 1.0194x; 1.0194x over previous
#include <cuda_runtime.h>
#include <cstdint>

#define BATCH 2048
#define NCLS  1000
#define DIM   128
#define TM 128
#define TN 128
#define NCTA 128
#define SROW 132            // f32 smem row stride in floats (528B: conflict-free)

// deterministic likelihood partials + completion ticket
__device__ __align__(16) float g_part[NCTA];
__device__ int g_ticket;

// ---- smem byte offsets ----
#define OFF_A   0                       // A f32 tile: 128 x 528B = 67584
#define OFF_B   67584                   // B f32 tile: 128 x 528B = 67584
#define OFF_FNP 135168                  // float[128][4] feat norm partials
#define OFF_CNP 137216                  // float[128][4] center norm partials
#define OFF_FNC 139264                  // float[128] 0.5*||f||^2
#define OFF_CNC 139776                  // float[128] 0.5*||c||^2
#define OFF_RED 140288                  // float[16] warp partials
#define SMEM_BYTES 140352

static __device__ __forceinline__ uint32_t smem_u32(const void* p) {
    uint32_t a;
    asm("{ .reg .u64 t; cvta.to.shared.u64 t, %1; cvt.u32.u64 %0, t; }"
        : "=r"(a) : "l"(p));
    return a;
}

static __device__ __forceinline__ int get_label(const void* lab, int b, int is64) {
    if (is64) return (int)(((const long long*)lab)[b]);
    return ((const int*)lab)[b];
}

static __device__ __forceinline__ void cp_async16(uint32_t saddr, const void* gptr) {
    asm volatile("cp.async.cg.shared.global [%0], [%1], 16;"
                 :: "r"(saddr), "l"(gptr) : "memory");
}
// zero-fill variant: src-size selects 16 (copy) or 0 (write 16B of zeros)
static __device__ __forceinline__ void cp_async16z(uint32_t saddr, const void* gptr,
                                                   uint32_t srcsz) {
    asm volatile("cp.async.cg.shared.global [%0], [%1], 16, %2;"
                 :: "r"(saddr), "l"(gptr), "r"(srcsz) : "memory");
}

// m16n8k8 tf32 MMA: raw f32 bits in A/B registers (HW truncates to tf32)
#define MMA1688(d, a0, a1, a2, a3, b0, b1)                                      \
    asm volatile("mma.sync.aligned.m16n8k8.row.col.f32.tf32.tf32.f32 "          \
        "{%0,%1,%2,%3}, {%4,%5,%6,%7}, {%8,%9}, {%0,%1,%2,%3};"                 \
        : "+f"((d)[0]), "+f"((d)[1]), "+f"((d)[2]), "+f"((d)[3])                \
        : "r"(a0), "r"(a1), "r"(a2), "r"(a3), "r"(b0), "r"(b1))

// ---------------------------------------------------------------------------
// Single kernel: cp.async f32 tiles -> in-smem norms -> tf32 MMA -> epilogue.
// Grid (8,16): CTA (x,y) -> rows [128y,128y+128) x cols [128x,128x+128).
// ---------------------------------------------------------------------------
__global__ void __launch_bounds__(512, 1)
lgm_tf32_kernel(const float* __restrict__ feat,
                const void*  __restrict__ label,
                const float* __restrict__ centers,
                float* __restrict__ logits,
                float* __restrict__ mlogits,
                float* __restrict__ lik)
{
    extern __shared__ char smem[];
    const uint32_t sb = smem_u32(smem);
    float* smf = (float*)smem;
    const int tid = threadIdx.x;
    const int wid  = tid >> 5;
    const int lane = tid & 31;
    const int bb = blockIdx.y * TM;      // feat-row base
    const int cc = blockIdx.x * TN;      // center-col base

    // label dtype probe loads (overlap with staging): words <= 255, in-bounds
    int hw = 0;
    if (tid < 128) hw = (((const int*)label)[2 * tid + 1] != 0);

    // ------------- staging: cp.async f32 tiles (B zero-filled past NCLS) -----
    {
        const char* srcA = (const char*)(feat + (size_t)bb * DIM);
        const uint32_t soff = (tid >> 5) * 528 + (tid & 31) * 16;   // row,16B col
#pragma unroll
        for (int j = 0; j < 8; j++)
            cp_async16(sb + OFF_A + j * 16 * 528 + soff, srcA + j * 8192 + tid * 16);
#pragma unroll
        for (int j = 0; j < 8; j++) {
            const int crow = cc + j * 16 + (tid >> 5);
            const int cr = crow < NCLS ? crow : NCLS - 1;
            cp_async16z(sb + OFF_B + j * 16 * 528 + soff,
                        (const char*)(centers + (size_t)cr * DIM) + (tid & 31) * 16,
                        crow < NCLS ? 16u : 0u);
        }
        asm volatile("cp.async.commit_group;" ::: "memory");
    }
    asm volatile("cp.async.wait_group 0;" ::: "memory");
    const int is64 = !__syncthreads_or(hw);   // barrier: tiles visible

    // ------------- preload epilogue labels (overlaps norm pass) --------------
    const int wm = wid & 3;
    const int wn = wid >> 2;
    const int g  = lane >> 2;
    const int tc = lane & 3;
    int labs[4];
#pragma unroll
    for (int mi = 0; mi < 2; mi++)
#pragma unroll
        for (int rr = 0; rr < 2; rr++)
            labs[mi * 2 + rr] =
                get_label(label, bb + wm * 32 + mi * 16 + g + rr * 8, is64);

    // ------------- norms from smem tiles (exact f32) -------------------------
    {
        const int r = tid & 127, q = tid >> 7;   // row, 32-col quarter
        const float4* ar = (const float4*)(smf + r * SROW + q * 32);
        const float4* br = (const float4*)(smf + OFF_B / 4 + r * SROW + q * 32);
        float sa = 0.f, sc = 0.f;
#pragma unroll
        for (int i = 0; i < 8; i++) {
            float4 v = ar[i];
            sa += v.x * v.x + v.y * v.y + v.z * v.z + v.w * v.w;
            float4 w = br[i];
            sc += w.x * w.x + w.y * w.y + w.z * w.z + w.w * w.w;
        }
        ((float*)(smem + OFF_FNP))[r * 4 + q] = sa;
        ((float*)(smem + OFF_CNP))[r * 4 + q] = sc;
    }
    __syncthreads();
    if (tid < 128) {
        const float* fp = (const float*)(smem + OFF_FNP) + tid * 4;
        const float* cp = (const float*)(smem + OFF_CNP) + tid * 4;
        ((float*)(smem + OFF_FNC))[tid] = 0.5f * ((fp[0] + fp[1]) + (fp[2] + fp[3]));
        ((float*)(smem + OFF_CNC))[tid] = 0.5f * ((cp[0] + cp[1]) + (cp[2] + cp[3]));
    }
    __syncthreads();

    // ------------- tf32 mainloop: warp = 32(M) x 32(N), K in 16 steps of 8 ---
    // A frag (m16k8): a0=(g,tc) a1=(g+8,tc) a2=(g,tc+4) a3=(g+8,tc+4)
    // B frag (k8n8):  b0=(k=tc,n=g) b1=(k=tc+4,n=g); B stored [n][k]
    const uint32_t* ap = (const uint32_t*)(smf + (wm * 32 + g) * SROW + tc);
    const uint32_t* bp = (const uint32_t*)(smf + OFF_B / 4 + (wn * 32 + g) * SROW + tc);

    float acc[2][4][4] = {};
#pragma unroll
    for (int k8 = 0; k8 < 16; k8++) {
        const int ko = k8 * 8;
        uint32_t a[2][4], b[4][2];
#pragma unroll
        for (int mi = 0; mi < 2; mi++) {
            const uint32_t* p = ap + mi * 16 * SROW + ko;
            a[mi][0] = p[0];
            a[mi][2] = p[4];
            a[mi][1] = p[8 * SROW];
            a[mi][3] = p[8 * SROW + 4];
        }
#pragma unroll
        for (int nb = 0; nb < 4; nb++) {
            const uint32_t* p = bp + nb * 8 * SROW + ko;
            b[nb][0] = p[0];
            b[nb][1] = p[4];
        }
#pragma unroll
        for (int mi = 0; mi < 2; mi++)
#pragma unroll
            for (int nb = 0; nb < 4; nb++)
                MMA1688(acc[mi][nb], a[mi][0], a[mi][1], a[mi][2], a[mi][3],
                        b[nb][0], b[nb][1]);
    }

    // ------------- direct-store epilogue -------------------------------------
    const float* fnc = (const float*)(smem + OFF_FNC);
    const float* cnc = (const float*)(smem + OFF_CNC);

    float lacc = 0.f;
#pragma unroll
    for (int mi = 0; mi < 2; mi++) {
#pragma unroll
        for (int rr = 0; rr < 2; rr++) {
            const int rloc = wm * 32 + mi * 16 + g + rr * 8;
            const int m  = bb + rloc;
            const float fn = fnc[rloc];
            const int lb = labs[mi * 2 + rr];
#pragma unroll
            for (int nb = 0; nb < 4; nb++) {
                const int cloc = wn * 32 + nb * 8 + tc * 2;
                const int c = cc + cloc;
                const float2 cn = *(const float2*)(cnc + cloc);
                const float d0 = acc[mi][nb][rr * 2 + 0];
                const float d1 = acc[mi][nb][rr * 2 + 1];
                // logits = -0.5*dist = dot - 0.5||f||^2 - 0.5||c||^2
                const float lg0 = d0 - fn - cn.x;
                const float lg1 = d1 - fn - cn.y;
                float ml0 = lg0, ml1 = lg1;
                if (lb == c)     { ml0 = 2.f * lg0; lacc += lg0; }
                if (lb == c + 1) { ml1 = 2.f * lg1; lacc += lg1; }
                if (c < NCLS) {
                    const size_t off = (size_t)m * NCLS + c;
                    *(float2*)(logits + off)  = make_float2(lg0, lg1);
                    *(float2*)(mlogits + off) = make_float2(ml0, ml1);
                }
            }
        }
    }

    // ------------- likelihood: warp reduce -> CTA partial -> last CTA ---------
#pragma unroll
    for (int o = 16; o > 0; o >>= 1)
        lacc += __shfl_xor_sync(0xffffffffu, lacc, o);
    float* red = (float*)(smem + OFF_RED);
    if (lane == 0) red[wid] = lacc;
    __syncthreads();

    if (tid == 0) {
        float s = (((red[0] + red[1]) + (red[2] + red[3]))
                 + ((red[4] + red[5]) + (red[6] + red[7])))
                + (((red[8] + red[9]) + (red[10] + red[11]))
                 + ((red[12] + red[13]) + (red[14] + red[15])));
        const int cid = blockIdx.y * 8 + blockIdx.x;
        g_part[cid] = s;
        __threadfence();
        int t = atomicAdd(&g_ticket, 1);
        if (t == NCTA - 1) {
            __threadfence();
            // fixed-order, fixed-split sum => deterministic
            float a0 = 0.f, a1 = 0.f, a2 = 0.f, a3 = 0.f;
            const float4* p4 = (const float4*)g_part;
#pragma unroll
            for (int i = 0; i < NCTA / 4; i++) {
                float4 v = p4[i];
                a0 += v.x; a1 += v.y; a2 += v.z; a3 += v.w;
            }
            *lik = -((a0 + a1) + (a2 + a3)) * (1.f / (float)BATCH);
            g_ticket = 0;          // reset for next graph replay
        }
    }
}

extern "C" void kernel_launch(void* const* d_in, const int* in_sizes, int n_in,
                              void* d_out, int out_size) {
    const float* feat    = (const float*)d_in[0];
    const void*  label   = d_in[1];
    const float* centers = (const float*)d_in[2];

    float* out     = (float*)d_out;
    float* logits  = out;                              // [B, C]
    float* mlogits = out + (size_t)BATCH * NCLS;       // [B, C]
    float* lik     = out + 2 * (size_t)BATCH * NCLS;   // scalar

    cudaFuncSetAttribute(lgm_tf32_kernel,
                         cudaFuncAttributeMaxDynamicSharedMemorySize, SMEM_BYTES);

    dim3 grid(8, 16);   // 128 CTAs of 128x128 — single launch, no prepass
    lgm_tf32_kernel<<<grid, 512, SMEM_BYTES>>>(feat, label, centers,
                                               logits, mlogits, lik);
}